// round 1
// baseline (speedup 1.0000x reference)
#include <cuda_runtime.h>

// Problem dims (fixed by dataset):
// features [64,50,4096] -> A [3200, 4096]
// phrases  [64,50,15,1024]
// W        [1024, 4096]
// b        [1024]
// phrase_lengths int32 [3200]
// out      [3200, 2048]  (cols 0..1023 = relu(A@W^T+b), cols 1024..2047 = mean phrase)

#define M_DIM 3200
#define N_DIM 1024
#define K_DIM 4096
#define OUT_STRIDE 2048
#define L_DIM 15
#define D_DIM 1024

#define BM 128
#define BN 64
#define BK 16
#define TM 8
#define TN 4
// 256 threads: 16 groups along M (TM=8) x 16 groups along N (TN=4)

__global__ __launch_bounds__(256, 2)
void gemm_relu_kernel(const float* __restrict__ A,
                      const float* __restrict__ W,
                      const float* __restrict__ bias,
                      float* __restrict__ out)
{
    __shared__ float As[BK][BM];   // transposed: As[k][m]
    __shared__ float Bs[BK][BN];   // transposed: Bs[k][n]

    const int bm = blockIdx.y * BM;
    const int bn = blockIdx.x * BN;
    const int tid = threadIdx.x;
    const int tm = (tid >> 4) * TM;   // 0..120
    const int tn = (tid & 15) * TN;   // 0..60

    float acc[TM][TN];
#pragma unroll
    for (int i = 0; i < TM; i++)
#pragma unroll
        for (int j = 0; j < TN; j++) acc[i][j] = 0.0f;

    // Loader mapping for A tile: 128 rows x 16 k = 512 float4 (4 f4 per row).
    // id = tid + s*256 ; row = id/4 ; kq = id%4
    // Loader mapping for B tile: 64 rows x 16 k = 256 float4, 1 per thread.
    const int a_row0 = tid >> 2;         // for s=0: rows 0..63
    const int a_kq   = tid & 3;
    const int b_row  = tid >> 2;         // 0..63
    const int b_kq   = tid & 3;

    for (int kt = 0; kt < K_DIM; kt += BK) {
        // --- load A tile (2 float4 per thread) ---
#pragma unroll
        for (int s = 0; s < 2; s++) {
            int row = a_row0 + s * 64;
            float4 v = *reinterpret_cast<const float4*>(
                A + (size_t)(bm + row) * K_DIM + kt + a_kq * 4);
            As[a_kq * 4 + 0][row] = v.x;
            As[a_kq * 4 + 1][row] = v.y;
            As[a_kq * 4 + 2][row] = v.z;
            As[a_kq * 4 + 3][row] = v.w;
        }
        // --- load B tile (1 float4 per thread) ---
        {
            float4 v = *reinterpret_cast<const float4*>(
                W + (size_t)(bn + b_row) * K_DIM + kt + b_kq * 4);
            Bs[b_kq * 4 + 0][b_row] = v.x;
            Bs[b_kq * 4 + 1][b_row] = v.y;
            Bs[b_kq * 4 + 2][b_row] = v.z;
            Bs[b_kq * 4 + 3][b_row] = v.w;
        }
        __syncthreads();

#pragma unroll
        for (int k = 0; k < BK; k++) {
            float a_reg[TM];
            float b_reg[TN];
#pragma unroll
            for (int i = 0; i < TM; i += 4) {
                float4 v = *reinterpret_cast<const float4*>(&As[k][tm + i]);
                a_reg[i + 0] = v.x; a_reg[i + 1] = v.y;
                a_reg[i + 2] = v.z; a_reg[i + 3] = v.w;
            }
            {
                float4 v = *reinterpret_cast<const float4*>(&Bs[k][tn]);
                b_reg[0] = v.x; b_reg[1] = v.y; b_reg[2] = v.z; b_reg[3] = v.w;
            }
#pragma unroll
            for (int i = 0; i < TM; i++)
#pragma unroll
                for (int j = 0; j < TN; j++)
                    acc[i][j] = fmaf(a_reg[i], b_reg[j], acc[i][j]);
        }
        __syncthreads();
    }

    // epilogue: bias + relu, vectorized float4 stores (tn multiple of 4)
    float4 bv = *reinterpret_cast<const float4*>(bias + bn + tn);
#pragma unroll
    for (int i = 0; i < TM; i++) {
        float4 r;
        r.x = fmaxf(acc[i][0] + bv.x, 0.0f);
        r.y = fmaxf(acc[i][1] + bv.y, 0.0f);
        r.z = fmaxf(acc[i][2] + bv.z, 0.0f);
        r.w = fmaxf(acc[i][3] + bv.w, 0.0f);
        *reinterpret_cast<float4*>(
            out + (size_t)(bm + tm + i) * OUT_STRIDE + bn + tn) = r;
    }
}

// Segment mean over L=15 tokens: out[row][1024 + d] = sum_l phrases[row][l][d] / len[row]
__global__ __launch_bounds__(256)
void phrase_mean_kernel(const float* __restrict__ phrases,
                        const int* __restrict__ lens,
                        float* __restrict__ out)
{
    const int row = blockIdx.x;          // 0..3199
    const int d4  = threadIdx.x;         // 0..255 (float4 index over D=1024)
    const float4* p = reinterpret_cast<const float4*>(
        phrases + (size_t)row * L_DIM * D_DIM) + d4;

    float4 s = make_float4(0.f, 0.f, 0.f, 0.f);
#pragma unroll
    for (int l = 0; l < L_DIM; l++) {
        float4 v = p[l * (D_DIM / 4)];
        s.x += v.x; s.y += v.y; s.z += v.z; s.w += v.w;
    }
    const float inv = 1.0f / (float)lens[row];
    s.x *= inv; s.y *= inv; s.z *= inv; s.w *= inv;
    reinterpret_cast<float4*>(out + (size_t)row * OUT_STRIDE + D_DIM)[d4] = s;
}

extern "C" void kernel_launch(void* const* d_in, const int* in_sizes, int n_in,
                              void* d_out, int out_size)
{
    const float* features = (const float*)d_in[0];   // [3200, 4096]
    const float* phrases  = (const float*)d_in[1];   // [3200, 15, 1024]
    const float* W        = (const float*)d_in[2];   // [1024, 4096]
    const float* bias     = (const float*)d_in[3];   // [1024]
    const int*   lens     = (const int*)d_in[4];     // [3200]
    float* out = (float*)d_out;                      // [3200, 2048]

    dim3 gemm_grid(N_DIM / BN, M_DIM / BM);          // (16, 25)
    gemm_relu_kernel<<<gemm_grid, 256>>>(features, W, bias, out);

    phrase_mean_kernel<<<M_DIM, 256>>>(phrases, lens, out);
}

// round 3
// speedup vs baseline: 2.2580x; 2.2580x over previous
#include <cuda_runtime.h>
#include <cuda_bf16.h>
#include <cstdint>

// Problem dims (fixed):
// features [3200, 4096] f32, phrases [3200, 15, 1024] f32,
// W [1024, 4096] f32, b [1024] f32, phrase_lengths [3200] i32
// out [3200, 2048] f32 : cols 0..1023 = relu(A@W^T + b), cols 1024..2047 = phrase mean
#define M_DIM 3200
#define N_DIM 1024
#define K_DIM 4096
#define OUT_STRIDE 2048
#define L_DIM 15
#define D_DIM 1024

// ---------------- device-global split buffers (bf16 hi/lo of A and W) ----------------
__device__ __nv_bfloat16 g_Ahi[(size_t)M_DIM * K_DIM];
__device__ __nv_bfloat16 g_Alo[(size_t)M_DIM * K_DIM];
__device__ __nv_bfloat16 g_Whi[(size_t)N_DIM * K_DIM];
__device__ __nv_bfloat16 g_Wlo[(size_t)N_DIM * K_DIM];

// ---------------- helpers ----------------
__device__ __forceinline__ uint32_t smem_to_u32(const void* p) {
    uint32_t a;
    asm("{ .reg .u64 t; cvta.to.shared.u64 t, %1; cvt.u32.u64 %0, t; }" : "=r"(a) : "l"(p));
    return a;
}
__device__ __forceinline__ void cp16(uint32_t dst, const void* src) {
    asm volatile("cp.async.cg.shared.global [%0], [%1], 16;" :: "r"(dst), "l"(src) : "memory");
}
#define CP_COMMIT() asm volatile("cp.async.commit_group;" ::: "memory")
#define CP_WAIT1()  asm volatile("cp.async.wait_group 1;" ::: "memory")
#define CP_WAIT0()  asm volatile("cp.async.wait_group 0;" ::: "memory")

__device__ __forceinline__ void ldm_x4(uint32_t* r, uint32_t addr) {
    asm volatile("ldmatrix.sync.aligned.m8n8.x4.shared.b16 {%0,%1,%2,%3}, [%4];"
                 : "=r"(r[0]), "=r"(r[1]), "=r"(r[2]), "=r"(r[3]) : "r"(addr));
}
__device__ __forceinline__ void mma16816(float* c, const uint32_t* a, uint32_t b0, uint32_t b1) {
    asm volatile(
        "mma.sync.aligned.m16n8k16.row.col.f32.bf16.bf16.f32 "
        "{%0,%1,%2,%3}, {%4,%5,%6,%7}, {%8,%9}, {%0,%1,%2,%3};"
        : "+f"(c[0]), "+f"(c[1]), "+f"(c[2]), "+f"(c[3])
        : "r"(a[0]), "r"(a[1]), "r"(a[2]), "r"(a[3]), "r"(b0), "r"(b1));
}

// ---------------- split prepass: fp32 -> bf16 hi + bf16 lo ----------------
__device__ __forceinline__ void split4(const float4 v, __nv_bfloat162* hi2, __nv_bfloat162* lo2, int i) {
    __nv_bfloat16 hx = __float2bfloat16(v.x);
    __nv_bfloat16 hy = __float2bfloat16(v.y);
    __nv_bfloat16 hz = __float2bfloat16(v.z);
    __nv_bfloat16 hw = __float2bfloat16(v.w);
    hi2[2 * i]     = __halves2bfloat162(hx, hy);
    hi2[2 * i + 1] = __halves2bfloat162(hz, hw);
    lo2[2 * i]     = __floats2bfloat162_rn(v.x - __bfloat162float(hx), v.y - __bfloat162float(hy));
    lo2[2 * i + 1] = __floats2bfloat162_rn(v.z - __bfloat162float(hz), v.w - __bfloat162float(hw));
}
__global__ __launch_bounds__(256) void split_A_kernel(const float* __restrict__ src) {
    const int n4 = M_DIM * K_DIM / 4;
    const float4* s4 = reinterpret_cast<const float4*>(src);
    __nv_bfloat162* hi2 = reinterpret_cast<__nv_bfloat162*>(g_Ahi);
    __nv_bfloat162* lo2 = reinterpret_cast<__nv_bfloat162*>(g_Alo);
    for (int i = blockIdx.x * blockDim.x + threadIdx.x; i < n4; i += gridDim.x * blockDim.x)
        split4(s4[i], hi2, lo2, i);
}
__global__ __launch_bounds__(256) void split_W_kernel(const float* __restrict__ src) {
    const int n4 = N_DIM * K_DIM / 4;
    const float4* s4 = reinterpret_cast<const float4*>(src);
    __nv_bfloat162* hi2 = reinterpret_cast<__nv_bfloat162*>(g_Whi);
    __nv_bfloat162* lo2 = reinterpret_cast<__nv_bfloat162*>(g_Wlo);
    for (int i = blockIdx.x * blockDim.x + threadIdx.x; i < n4; i += gridDim.x * blockDim.x)
        split4(s4[i], hi2, lo2, i);
}

// ---------------- mma.sync GEMM: out[:, 0:1024] = relu(A@W^T + b) ----------------
// BM=128, BN=64, BK=32 (bf16). 8 warps, warp grid 4x2, warp tile 32x32.
// 3-stage cp.async pipeline. Padded smem rows: 64B data + 16B pad = 80B stride
// (stride/16 = 5 -> row*5 mod 8 is a permutation -> conflict-free ldmatrix).
#define BK 32
#define NC (K_DIM / BK)          // 128
#define ROW_B 80                 // bytes per smem row
#define A_TILE (128 * ROW_B)     // 10240
#define B_TILE (64 * ROW_B)      // 5120
#define STAGE_BYTES (2 * A_TILE + 2 * B_TILE)   // 30720
#define NSTAGE 3
#define GEMM_SMEM (NSTAGE * STAGE_BYTES)        // 92160

__global__ __launch_bounds__(256, 2)
void gemm_mma_kernel(const float* __restrict__ bias, float* __restrict__ out) {
    extern __shared__ char smem[];
    const uint32_t sbase = smem_to_u32(smem);
    const int tid = threadIdx.x;
    const int wid = tid >> 5;
    const int lane = tid & 31;
    const int wm = wid >> 1;            // 0..3  (rows wm*32 .. +31)
    const int wn = wid & 1;             // 0..1  (cols wn*32 .. +31)
    const int bm = blockIdx.y * 128;
    const int bn = blockIdx.x * 64;

    // loader indices
    const int a_row = tid >> 2;         // +0 / +64
    const int a_c   = tid & 3;
    const int b_row = tid >> 2;         // 0..63
    const int b_c   = tid & 3;

    auto load_chunk = [&](int chunk, int stage) {
        const int kt = chunk * BK;
        const uint32_t sb = sbase + (uint32_t)stage * STAGE_BYTES;
#pragma unroll
        for (int j = 0; j < 2; j++) {
            const int row = a_row + j * 64;
            const uint32_t off = (uint32_t)(row * ROW_B + a_c * 16);
            const size_t ga = (size_t)(bm + row) * K_DIM + kt + a_c * 8;
            cp16(sb + off,          g_Ahi + ga);
            cp16(sb + A_TILE + off, g_Alo + ga);
        }
        {
            const uint32_t off = (uint32_t)(b_row * ROW_B + b_c * 16);
            const size_t gb = (size_t)(bn + b_row) * K_DIM + kt + b_c * 8;
            cp16(sb + 2 * A_TILE + off,          g_Whi + gb);
            cp16(sb + 2 * A_TILE + B_TILE + off, g_Wlo + gb);
        }
    };

    float acc[2][4][4];
#pragma unroll
    for (int t = 0; t < 2; t++)
#pragma unroll
        for (int j = 0; j < 4; j++)
#pragma unroll
            for (int q = 0; q < 4; q++) acc[t][j][q] = 0.0f;

    // lane-dependent address components (byte offsets within a tile array)
    // A (ldmatrix x4 over m16,k16): row = wm*32 + t*16 + (lane&15), koff = ks*32B.. + (lane>>4)*16
    const uint32_t a_lrow = (uint32_t)(wm * 32 + (lane & 15));
    const uint32_t a_lkof = (uint32_t)((lane >> 4) << 4);
    // B (ldmatrix x4 over two n8 tiles x k16): grp = lane>>3
    const int grp = lane >> 3;
    const uint32_t b_ln   = (uint32_t)(wn * 32 + ((grp >> 1) << 3) + (lane & 7));
    const uint32_t b_lkof = (uint32_t)((grp & 1) << 4);

    load_chunk(0, 0); CP_COMMIT();
    load_chunk(1, 1); CP_COMMIT();

    for (int c = 0; c < NC; c++) {
        if (c < NC - 1) { CP_WAIT1(); } else { CP_WAIT0(); }
        __syncthreads();

        const int nx = c + 2;
        if (nx < NC) { load_chunk(nx, nx % NSTAGE); CP_COMMIT(); }

        const uint32_t sb = sbase + (uint32_t)(c % NSTAGE) * STAGE_BYTES;
        const uint32_t sAhi = sb;
        const uint32_t sAlo = sb + A_TILE;
        const uint32_t sBhi = sb + 2 * A_TILE;
        const uint32_t sBlo = sb + 2 * A_TILE + B_TILE;

#pragma unroll
        for (int ks = 0; ks < 2; ks++) {
            uint32_t ah[2][4], al[2][4], bh[2][4], bl[2][4];
            const uint32_t akoff = (uint32_t)(ks * 32) + a_lkof;
            const uint32_t bkoff = (uint32_t)(ks * 32) + b_lkof;
#pragma unroll
            for (int t = 0; t < 2; t++) {
                const uint32_t aoff = (a_lrow + t * 16) * ROW_B + akoff;
                ldm_x4(ah[t], sAhi + aoff);
                ldm_x4(al[t], sAlo + aoff);
            }
#pragma unroll
            for (int p = 0; p < 2; p++) {
                const uint32_t boff = (b_ln + p * 16) * ROW_B + bkoff;
                ldm_x4(bh[p], sBhi + boff);
                ldm_x4(bl[p], sBlo + boff);
            }
#pragma unroll
            for (int t = 0; t < 2; t++) {
#pragma unroll
                for (int j = 0; j < 4; j++) {
                    const int p = j >> 1;
                    const int s = (j & 1) * 2;
                    mma16816(acc[t][j], ah[t], bh[p][s], bh[p][s + 1]);
                    mma16816(acc[t][j], ah[t], bl[p][s], bl[p][s + 1]);
                    mma16816(acc[t][j], al[t], bh[p][s], bh[p][s + 1]);
                }
            }
        }
    }

    // epilogue: bias + relu. c0,c1 -> (row, col..col+1); c2,c3 -> (row+8, ...)
    const int g  = lane >> 2;
    const int tg = lane & 3;
#pragma unroll
    for (int t = 0; t < 2; t++) {
#pragma unroll
        for (int j = 0; j < 4; j++) {
            const int col = wn * 32 + j * 8 + tg * 2;
            const float b0 = bias[bn + col];
            const float b1 = bias[bn + col + 1];
            const int row0 = bm + wm * 32 + t * 16 + g;
            float2 v0, v1;
            v0.x = fmaxf(acc[t][j][0] + b0, 0.0f);
            v0.y = fmaxf(acc[t][j][1] + b1, 0.0f);
            v1.x = fmaxf(acc[t][j][2] + b0, 0.0f);
            v1.y = fmaxf(acc[t][j][3] + b1, 0.0f);
            *reinterpret_cast<float2*>(out + (size_t)row0 * OUT_STRIDE + bn + col) = v0;
            *reinterpret_cast<float2*>(out + (size_t)(row0 + 8) * OUT_STRIDE + bn + col) = v1;
        }
    }
}

// ---------------- phrase mean: out[:, 1024:2048] ----------------
__global__ __launch_bounds__(256)
void phrase_mean_kernel(const float* __restrict__ phrases,
                        const int* __restrict__ lens,
                        float* __restrict__ out) {
    const int row = blockIdx.x;
    const int d4 = threadIdx.x;
    const float4* p = reinterpret_cast<const float4*>(phrases + (size_t)row * L_DIM * D_DIM) + d4;
    float4 s = make_float4(0.f, 0.f, 0.f, 0.f);
#pragma unroll
    for (int l = 0; l < L_DIM; l++) {
        float4 v = p[l * (D_DIM / 4)];
        s.x += v.x; s.y += v.y; s.z += v.z; s.w += v.w;
    }
    const float inv = 1.0f / (float)lens[row];
    s.x *= inv; s.y *= inv; s.z *= inv; s.w *= inv;
    reinterpret_cast<float4*>(out + (size_t)row * OUT_STRIDE + D_DIM)[d4] = s;
}

// ---------------- launch ----------------
extern "C" void kernel_launch(void* const* d_in, const int* in_sizes, int n_in,
                              void* d_out, int out_size) {
    const float* features = (const float*)d_in[0];
    const float* phrases  = (const float*)d_in[1];
    const float* W        = (const float*)d_in[2];
    const float* bias     = (const float*)d_in[3];
    const int*   lens     = (const int*)d_in[4];
    float* out = (float*)d_out;

    cudaFuncSetAttribute(gemm_mma_kernel, cudaFuncAttributeMaxDynamicSharedMemorySize, GEMM_SMEM);

    split_A_kernel<<<2048, 256>>>(features);
    split_W_kernel<<<1024, 256>>>(W);
    phrase_mean_kernel<<<M_DIM, 256>>>(phrases, lens, out);

    dim3 grid(N_DIM / 64, M_DIM / 128);   // (16, 25) = 400 CTAs
    gemm_mma_kernel<<<grid, 256, GEMM_SMEM>>>(bias, out);
}

// round 4
// speedup vs baseline: 2.2771x; 1.0085x over previous
#include <cuda_runtime.h>
#include <cuda_bf16.h>
#include <cstdint>

// Problem dims (fixed):
// features [3200, 4096] f32, phrases [3200, 15, 1024] f32,
// W [1024, 4096] f32, b [1024] f32, phrase_lengths [3200] i32
// out [3200, 2048] f32 : cols 0..1023 = relu(A@W^T + b), cols 1024..2047 = phrase mean
#define M_DIM 3200
#define N_DIM 1024
#define K_DIM 4096
#define OUT_STRIDE 2048
#define L_DIM 15
#define D_DIM 1024
#define KSPLIT 2
#define KHALF (K_DIM / KSPLIT)   // 2048

// ---------------- device-global buffers ----------------
__device__ __nv_bfloat16 g_Ahi[(size_t)M_DIM * K_DIM];
__device__ __nv_bfloat16 g_Alo[(size_t)M_DIM * K_DIM];
__device__ __nv_bfloat16 g_Whi[(size_t)N_DIM * K_DIM];
__device__ __nv_bfloat16 g_Wlo[(size_t)N_DIM * K_DIM];
__device__ float g_part[(size_t)KSPLIT * M_DIM * N_DIM];   // 26.2 MB partials

// ---------------- helpers ----------------
__device__ __forceinline__ uint32_t smem_to_u32(const void* p) {
    uint32_t a;
    asm("{ .reg .u64 t; cvta.to.shared.u64 t, %1; cvt.u32.u64 %0, t; }" : "=r"(a) : "l"(p));
    return a;
}
__device__ __forceinline__ void cp16(uint32_t dst, const void* src) {
    asm volatile("cp.async.cg.shared.global [%0], [%1], 16;" :: "r"(dst), "l"(src) : "memory");
}
#define CP_COMMIT() asm volatile("cp.async.commit_group;" ::: "memory")
#define CP_WAIT1()  asm volatile("cp.async.wait_group 1;" ::: "memory")
#define CP_WAIT0()  asm volatile("cp.async.wait_group 0;" ::: "memory")

__device__ __forceinline__ void ldm_x4(uint32_t* r, uint32_t addr) {
    asm volatile("ldmatrix.sync.aligned.m8n8.x4.shared.b16 {%0,%1,%2,%3}, [%4];"
                 : "=r"(r[0]), "=r"(r[1]), "=r"(r[2]), "=r"(r[3]) : "r"(addr));
}
__device__ __forceinline__ void mma16816(float* c, const uint32_t* a, uint32_t b0, uint32_t b1) {
    asm volatile(
        "mma.sync.aligned.m16n8k16.row.col.f32.bf16.bf16.f32 "
        "{%0,%1,%2,%3}, {%4,%5,%6,%7}, {%8,%9}, {%0,%1,%2,%3};"
        : "+f"(c[0]), "+f"(c[1]), "+f"(c[2]), "+f"(c[3])
        : "r"(a[0]), "r"(a[1]), "r"(a[2]), "r"(a[3]), "r"(b0), "r"(b1));
}

// ---------------- split prepass: fp32 -> bf16 hi + bf16 lo ----------------
__device__ __forceinline__ void split4(const float4 v, __nv_bfloat162* hi2, __nv_bfloat162* lo2, int i) {
    __nv_bfloat16 hx = __float2bfloat16(v.x);
    __nv_bfloat16 hy = __float2bfloat16(v.y);
    __nv_bfloat16 hz = __float2bfloat16(v.z);
    __nv_bfloat16 hw = __float2bfloat16(v.w);
    hi2[2 * i]     = __halves2bfloat162(hx, hy);
    hi2[2 * i + 1] = __halves2bfloat162(hz, hw);
    lo2[2 * i]     = __floats2bfloat162_rn(v.x - __bfloat162float(hx), v.y - __bfloat162float(hy));
    lo2[2 * i + 1] = __floats2bfloat162_rn(v.z - __bfloat162float(hz), v.w - __bfloat162float(hw));
}
__global__ __launch_bounds__(256) void split_A_kernel(const float* __restrict__ src) {
    const int n4 = M_DIM * K_DIM / 4;
    const float4* s4 = reinterpret_cast<const float4*>(src);
    __nv_bfloat162* hi2 = reinterpret_cast<__nv_bfloat162*>(g_Ahi);
    __nv_bfloat162* lo2 = reinterpret_cast<__nv_bfloat162*>(g_Alo);
    for (int i = blockIdx.x * blockDim.x + threadIdx.x; i < n4; i += gridDim.x * blockDim.x)
        split4(s4[i], hi2, lo2, i);
}
__global__ __launch_bounds__(256) void split_W_kernel(const float* __restrict__ src) {
    const int n4 = N_DIM * K_DIM / 4;
    const float4* s4 = reinterpret_cast<const float4*>(src);
    __nv_bfloat162* hi2 = reinterpret_cast<__nv_bfloat162*>(g_Whi);
    __nv_bfloat162* lo2 = reinterpret_cast<__nv_bfloat162*>(g_Wlo);
    for (int i = blockIdx.x * blockDim.x + threadIdx.x; i < n4; i += gridDim.x * blockDim.x)
        split4(s4[i], hi2, lo2, i);
}

// ---------------- mma.sync GEMM (split-K partials) ----------------
// BM=128, BN=64, BK=32 bf16. 8 warps, warp grid 4x2, warp tile 32x32.
// blockIdx.z selects K half. 3-stage cp.async pipeline, 80B padded smem rows.
#define BK 32
#define NC (KHALF / BK)          // 64
#define ROW_B 80
#define A_TILE (128 * ROW_B)
#define B_TILE (64 * ROW_B)
#define STAGE_BYTES (2 * A_TILE + 2 * B_TILE)   // 30720
#define NSTAGE 3
#define GEMM_SMEM (NSTAGE * STAGE_BYTES)        // 92160

__global__ __launch_bounds__(256, 2)
void gemm_mma_kernel() {
    extern __shared__ char smem[];
    const uint32_t sbase = smem_to_u32(smem);
    const int tid = threadIdx.x;
    const int wid = tid >> 5;
    const int lane = tid & 31;
    const int wm = wid >> 1;
    const int wn = wid & 1;
    const int bm = blockIdx.y * 128;
    const int bn = blockIdx.x * 64;
    const int kbase = blockIdx.z * KHALF;
    float* part = g_part + (size_t)blockIdx.z * M_DIM * N_DIM;

    const int a_row = tid >> 2;
    const int a_c   = tid & 3;

    auto load_chunk = [&](int chunk, int stage) {
        const int kt = kbase + chunk * BK;
        const uint32_t sb = sbase + (uint32_t)stage * STAGE_BYTES;
#pragma unroll
        for (int j = 0; j < 2; j++) {
            const int row = a_row + j * 64;
            const uint32_t off = (uint32_t)(row * ROW_B + a_c * 16);
            const size_t ga = (size_t)(bm + row) * K_DIM + kt + a_c * 8;
            cp16(sb + off,          g_Ahi + ga);
            cp16(sb + A_TILE + off, g_Alo + ga);
        }
        {
            const uint32_t off = (uint32_t)(a_row * ROW_B + a_c * 16);
            const size_t gb = (size_t)(bn + a_row) * K_DIM + kt + a_c * 8;
            cp16(sb + 2 * A_TILE + off,          g_Whi + gb);
            cp16(sb + 2 * A_TILE + B_TILE + off, g_Wlo + gb);
        }
    };

    float acc[2][4][4];
#pragma unroll
    for (int t = 0; t < 2; t++)
#pragma unroll
        for (int j = 0; j < 4; j++)
#pragma unroll
            for (int q = 0; q < 4; q++) acc[t][j][q] = 0.0f;

    const uint32_t a_lrow = (uint32_t)(wm * 32 + (lane & 15));
    const uint32_t a_lkof = (uint32_t)((lane >> 4) << 4);
    const int grp = lane >> 3;
    const uint32_t b_ln   = (uint32_t)(wn * 32 + ((grp >> 1) << 3) + (lane & 7));
    const uint32_t b_lkof = (uint32_t)((grp & 1) << 4);

    load_chunk(0, 0); CP_COMMIT();
    load_chunk(1, 1); CP_COMMIT();

    for (int c = 0; c < NC; c++) {
        if (c < NC - 1) { CP_WAIT1(); } else { CP_WAIT0(); }
        __syncthreads();

        const int nx = c + 2;
        if (nx < NC) { load_chunk(nx, nx % NSTAGE); CP_COMMIT(); }

        const uint32_t sb = sbase + (uint32_t)(c % NSTAGE) * STAGE_BYTES;
        const uint32_t sAhi = sb;
        const uint32_t sAlo = sb + A_TILE;
        const uint32_t sBhi = sb + 2 * A_TILE;
        const uint32_t sBlo = sb + 2 * A_TILE + B_TILE;

        // load ALL fragments for both k-steps first (prefetch), then MMA
        uint32_t ah[2][2][4], al[2][2][4], bh[2][2][4], bl[2][2][4];
#pragma unroll
        for (int ks = 0; ks < 2; ks++) {
            const uint32_t akoff = (uint32_t)(ks * 32) + a_lkof;
            const uint32_t bkoff = (uint32_t)(ks * 32) + b_lkof;
#pragma unroll
            for (int t = 0; t < 2; t++) {
                const uint32_t aoff = (a_lrow + t * 16) * ROW_B + akoff;
                ldm_x4(ah[ks][t], sAhi + aoff);
                ldm_x4(al[ks][t], sAlo + aoff);
            }
#pragma unroll
            for (int p = 0; p < 2; p++) {
                const uint32_t boff = (b_ln + p * 16) * ROW_B + bkoff;
                ldm_x4(bh[ks][p], sBhi + boff);
                ldm_x4(bl[ks][p], sBlo + boff);
            }
        }
#pragma unroll
        for (int ks = 0; ks < 2; ks++) {
#pragma unroll
            for (int t = 0; t < 2; t++) {
#pragma unroll
                for (int j = 0; j < 4; j++) {
                    const int p = j >> 1;
                    const int s = (j & 1) * 2;
                    mma16816(acc[t][j], ah[ks][t], bh[ks][p][s], bh[ks][p][s + 1]);
                    mma16816(acc[t][j], ah[ks][t], bl[ks][p][s], bl[ks][p][s + 1]);
                    mma16816(acc[t][j], al[ks][t], bh[ks][p][s], bh[ks][p][s + 1]);
                }
            }
        }
    }

    // epilogue: raw fp32 partials, stride N_DIM
    const int g  = lane >> 2;
    const int tg = lane & 3;
#pragma unroll
    for (int t = 0; t < 2; t++) {
#pragma unroll
        for (int j = 0; j < 4; j++) {
            const int col = bn + wn * 32 + j * 8 + tg * 2;
            const int row0 = bm + wm * 32 + t * 16 + g;
            float2 v0, v1;
            v0.x = acc[t][j][0]; v0.y = acc[t][j][1];
            v1.x = acc[t][j][2]; v1.y = acc[t][j][3];
            *reinterpret_cast<float2*>(part + (size_t)row0 * N_DIM + col) = v0;
            *reinterpret_cast<float2*>(part + (size_t)(row0 + 8) * N_DIM + col) = v1;
        }
    }
}

// ---------------- reduce: out[:,0:1024] = relu(p0 + p1 + bias) ----------------
__global__ __launch_bounds__(256)
void reduce_kernel(const float* __restrict__ bias, float* __restrict__ out) {
    const int row = blockIdx.x;
    const int c4 = threadIdx.x;          // float4 index over 1024 cols
    const size_t off = (size_t)row * (N_DIM / 4) + c4;
    const float4 p0 = reinterpret_cast<const float4*>(g_part)[off];
    const float4 p1 = reinterpret_cast<const float4*>(g_part + (size_t)M_DIM * N_DIM)[off];
    const float4 bv = reinterpret_cast<const float4*>(bias)[c4];
    float4 v;
    v.x = fmaxf(p0.x + p1.x + bv.x, 0.0f);
    v.y = fmaxf(p0.y + p1.y + bv.y, 0.0f);
    v.z = fmaxf(p0.z + p1.z + bv.z, 0.0f);
    v.w = fmaxf(p0.w + p1.w + bv.w, 0.0f);
    reinterpret_cast<float4*>(out + (size_t)row * OUT_STRIDE)[c4] = v;
}

// ---------------- phrase mean: out[:, 1024:2048] ----------------
__global__ __launch_bounds__(256)
void phrase_mean_kernel(const float* __restrict__ phrases,
                        const int* __restrict__ lens,
                        float* __restrict__ out) {
    const int row = blockIdx.x;
    const int d4 = threadIdx.x;
    const float4* p = reinterpret_cast<const float4*>(phrases + (size_t)row * L_DIM * D_DIM) + d4;
    float4 s = make_float4(0.f, 0.f, 0.f, 0.f);
#pragma unroll
    for (int l = 0; l < L_DIM; l++) {
        float4 v = p[l * (D_DIM / 4)];
        s.x += v.x; s.y += v.y; s.z += v.z; s.w += v.w;
    }
    const float inv = 1.0f / (float)lens[row];
    s.x *= inv; s.y *= inv; s.z *= inv; s.w *= inv;
    reinterpret_cast<float4*>(out + (size_t)row * OUT_STRIDE + D_DIM)[d4] = s;
}

// ---------------- launch ----------------
extern "C" void kernel_launch(void* const* d_in, const int* in_sizes, int n_in,
                              void* d_out, int out_size) {
    const float* features = (const float*)d_in[0];
    const float* phrases  = (const float*)d_in[1];
    const float* W        = (const float*)d_in[2];
    const float* bias     = (const float*)d_in[3];
    const int*   lens     = (const int*)d_in[4];
    float* out = (float*)d_out;

    cudaFuncSetAttribute(gemm_mma_kernel, cudaFuncAttributeMaxDynamicSharedMemorySize, GEMM_SMEM);

    split_A_kernel<<<2048, 256>>>(features);
    split_W_kernel<<<1024, 256>>>(W);
    phrase_mean_kernel<<<M_DIM, 256>>>(phrases, lens, out);

    dim3 grid(N_DIM / 64, M_DIM / 128, KSPLIT);   // (16, 25, 2) = 800 CTAs
    gemm_mma_kernel<<<grid, 256, GEMM_SMEM>>>();

    reduce_kernel<<<M_DIM, 256>>>(bias, out);
}